// round 2
// baseline (speedup 1.0000x reference)
#include <cuda_runtime.h>
#include <stdint.h>

// ---------------------------------------------------------------------------
// TopK Router: logits = x @ W^T  [16384,64], softmax, top-2
// x: [4,4096,4096] f32   W: [64,4096] f32   k=2
// out (f32): probs[16384*64] ++ indices[16384*2] ++ values[16384*2]
// ---------------------------------------------------------------------------

#define D_DIM   4096
#define E_DIM   64
#define NROWS   16384

#define ROWS_PER_BLK 128
#define THREADS      256
#define KC           64
#define NCHUNK       (D_DIM / KC)

#define XS_STRIDE 68
#define WS_STRIDE 68
#define LG_STRIDE 68
#define XS_BUF (ROWS_PER_BLK * XS_STRIDE)   // 8704 floats
#define WS_BUF (KC * WS_STRIDE)             // 4352 floats
#define LG_SIZE (ROWS_PER_BLK * LG_STRIDE)  // 8704 floats
#define SMEM_FLOATS (2*XS_BUF + 2*WS_BUF + LG_SIZE)
#define SMEM_BYTES  (SMEM_FLOATS * 4)       // 139264 B

// W transposed into [k][e] layout so cp.async can stream it k-major.
__device__ float g_Wt[D_DIM * E_DIM];

// ---------------- packed f32x2 helpers (Blackwell FFMA2 path) ---------------
__device__ __forceinline__ unsigned long long bcast2(float x) {
    unsigned long long r;
    unsigned u = __float_as_uint(x);
    asm("mov.b64 %0, {%1, %1};" : "=l"(r) : "r"(u));
    return r;
}
__device__ __forceinline__ void fma2(unsigned long long& acc,
                                     unsigned long long a,
                                     unsigned long long b) {
    asm("fma.rn.f32x2 %0, %1, %2, %0;" : "+l"(acc) : "l"(a), "l"(b));
}
__device__ __forceinline__ void add2(unsigned long long& acc,
                                     unsigned long long a) {
    asm("add.rn.f32x2 %0, %0, %1;" : "+l"(acc) : "l"(a));
}

// ---------------- cp.async helpers ------------------------------------------
__device__ __forceinline__ void cp16(uint32_t smem_addr, const void* gptr) {
    asm volatile("cp.async.cg.shared.global [%0], [%1], 16;"
                 :: "r"(smem_addr), "l"(gptr));
}
__device__ __forceinline__ void cp_commit() {
    asm volatile("cp.async.commit_group;");
}
__device__ __forceinline__ void cp_wait1() {
    asm volatile("cp.async.wait_group 1;");
}
__device__ __forceinline__ void cp_wait0() {
    asm volatile("cp.async.wait_group 0;");
}

// ---------------- W transpose kernel ----------------------------------------
__global__ void transpose_W(const float* __restrict__ W) {
    int gid = blockIdx.x * blockDim.x + threadIdx.x;  // 0 .. 262143
    int k = gid >> 6;
    int e = gid & 63;
    g_Wt[gid] = W[(size_t)e * D_DIM + k];
}

// ---------------- main fused kernel ------------------------------------------
__device__ __forceinline__ void load_chunk(uint32_t xs_s, uint32_t ws_s,
                                           const float* __restrict__ x,
                                           int row0, int c0, int t) {
    // x tile: 128 rows x 64 k  (2048 float4, 8 per thread)
#pragma unroll
    for (int it = 0; it < 8; ++it) {
        int id  = it * THREADS + t;
        int row = id >> 4;
        int q   = id & 15;
        cp16(xs_s + (uint32_t)(row * XS_STRIDE + q * 4) * 4,
             x + (size_t)(row0 + row) * D_DIM + c0 + q * 4);
    }
    // W tile (transposed): 64 k x 64 e (1024 float4, 4 per thread)
#pragma unroll
    for (int it = 0; it < 4; ++it) {
        int id = it * THREADS + t;
        int kk = id >> 4;
        int q  = id & 15;
        cp16(ws_s + (uint32_t)(kk * WS_STRIDE + q * 4) * 4,
             g_Wt + (size_t)(c0 + kk) * E_DIM + q * 4);
    }
    cp_commit();
}

__global__ void __launch_bounds__(THREADS, 1)
router_kernel(const float* __restrict__ x, float* __restrict__ out)
{
    extern __shared__ float sm[];
    float* xs = sm;                              // 2 x XS_BUF
    float* ws = sm + 2 * XS_BUF;                 // 2 x WS_BUF
    float* lg = sm + 2 * XS_BUF + 2 * WS_BUF;    // LG_SIZE

    const int t    = threadIdx.x;
    const int row0 = blockIdx.x * ROWS_PER_BLK;
    const int eg   = t & 7;    // experts [8*eg, 8*eg+8)
    const int rg   = t >> 3;   // rows    [4*rg, 4*rg+4)

    uint32_t xs_s = (uint32_t)__cvta_generic_to_shared(xs);
    uint32_t ws_s = (uint32_t)__cvta_generic_to_shared(ws);

    // main accumulators: 4 rows x 4 expert-pairs, packed f32x2
    unsigned long long accM[4][4];
#pragma unroll
    for (int i = 0; i < 4; ++i)
#pragma unroll
        for (int p = 0; p < 4; ++p) accM[i][p] = 0ull;

    load_chunk(xs_s, ws_s, x, row0, 0, t);

    for (int c = 0; c < NCHUNK; ++c) {
        const int buf = c & 1;
        if (c + 1 < NCHUNK) {
            load_chunk(xs_s + (uint32_t)(((c + 1) & 1) * XS_BUF) * 4,
                       ws_s + (uint32_t)(((c + 1) & 1) * WS_BUF) * 4,
                       x, row0, (c + 1) * KC, t);
            cp_wait1();
        } else {
            cp_wait0();
        }
        __syncthreads();

        const float* xb = xs + buf * XS_BUF + (4 * rg) * XS_STRIDE;
        const float* wb = ws + buf * WS_BUF + 8 * eg;

        // chunk-local accumulators (two-level accumulation for accuracy)
        unsigned long long acc[4][4];
#pragma unroll
        for (int i = 0; i < 4; ++i)
#pragma unroll
            for (int p = 0; p < 4; ++p) acc[i][p] = 0ull;

#pragma unroll 4
        for (int kq = 0; kq < 16; ++kq) {
            float xv[4][4];
#pragma unroll
            for (int i = 0; i < 4; ++i) {
                float4 v = *(const float4*)(xb + i * XS_STRIDE + kq * 4);
                xv[i][0] = v.x; xv[i][1] = v.y; xv[i][2] = v.z; xv[i][3] = v.w;
            }
#pragma unroll
            for (int kk = 0; kk < 4; ++kk) {
                const float* wrow = wb + (kq * 4 + kk) * WS_STRIDE;
                ulonglong2 w01 = *(const ulonglong2*)(wrow);
                ulonglong2 w23 = *(const ulonglong2*)(wrow + 4);
#pragma unroll
                for (int i = 0; i < 4; ++i) {
                    unsigned long long a = bcast2(xv[i][kk]);
                    fma2(acc[i][0], a, w01.x);
                    fma2(acc[i][1], a, w01.y);
                    fma2(acc[i][2], a, w23.x);
                    fma2(acc[i][3], a, w23.y);
                }
            }
        }
#pragma unroll
        for (int i = 0; i < 4; ++i)
#pragma unroll
            for (int p = 0; p < 4; ++p) add2(accM[i][p], acc[i][p]);

        __syncthreads();  // protect buf before it is refilled
    }

    // ---- write logits to smem ----
#pragma unroll
    for (int i = 0; i < 4; ++i)
#pragma unroll
        for (int p = 0; p < 4; ++p)
            *(unsigned long long*)(lg + (4 * rg + i) * LG_STRIDE + 8 * eg + 2 * p)
                = accM[i][p];
    __syncthreads();

    // ---- epilogue: softmax + top-2, one thread per row ----
    if (t < ROWS_PER_BLK) {
        float l[64];
#pragma unroll
        for (int j = 0; j < 16; ++j) {
            float4 v = *(const float4*)(lg + t * LG_STRIDE + 4 * j);
            l[4*j+0] = v.x; l[4*j+1] = v.y; l[4*j+2] = v.z; l[4*j+3] = v.w;
        }

        float mx = l[0];
#pragma unroll
        for (int j = 1; j < 64; ++j) mx = fmaxf(mx, l[j]);

        float v1 = -3.4e38f, v2 = -3.4e38f;
        int   i1 = 0,        i2 = 0;
#pragma unroll
        for (int j = 0; j < 64; ++j) {
            float lj = l[j];
            if (lj > v1) { v2 = v1; i2 = i1; v1 = lj; i1 = j; }
            else if (lj > v2) { v2 = lj; i2 = j; }
        }

        float p[64];
        float s = 0.f;
#pragma unroll
        for (int j = 0; j < 64; ++j) { p[j] = __expf(l[j] - mx); s += p[j]; }
        float inv = __fdividef(1.0f, s);

        const int grow = row0 + t;
        float* po = out + (size_t)grow * 64;
#pragma unroll
        for (int j = 0; j < 16; ++j) {
            float4 v;
            v.x = p[4*j+0] * inv; v.y = p[4*j+1] * inv;
            v.z = p[4*j+2] * inv; v.w = p[4*j+3] * inv;
            *(float4*)(po + 4 * j) = v;
        }

        float* io = out + (size_t)NROWS * 64;
        io[(size_t)grow * 2 + 0] = (float)i1;
        io[(size_t)grow * 2 + 1] = (float)i2;

        float* vo = out + (size_t)NROWS * 64 + (size_t)NROWS * 2;
        vo[(size_t)grow * 2 + 0] = __expf(v1 - mx) * inv;
        vo[(size_t)grow * 2 + 1] = __expf(v2 - mx) * inv;
    }
}

// ---------------------------------------------------------------------------
extern "C" void kernel_launch(void* const* d_in, const int* in_sizes, int n_in,
                              void* d_out, int out_size) {
    const float* x = (const float*)d_in[0];
    const float* W = (const float*)d_in[1];
    float* out = (float*)d_out;

    transpose_W<<<(D_DIM * E_DIM) / 256, 256>>>(W);

    cudaFuncSetAttribute(router_kernel,
                         cudaFuncAttributeMaxDynamicSharedMemorySize,
                         SMEM_BYTES);
    router_kernel<<<NROWS / ROWS_PER_BLK, THREADS, SMEM_BYTES>>>(x, out);
}

// round 4
// speedup vs baseline: 3.4087x; 3.4087x over previous
#include <cuda_runtime.h>
#include <cuda_fp16.h>
#include <stdint.h>

// ---------------------------------------------------------------------------
// TopK Router via warp-level mma.sync (HMMA), fp16x3 split GEMM.
// logits = x @ W^T : [16384, 64], softmax, top-2.
// x: [4,4096,4096] f32   W: [64,4096] f32
// out f32: probs[16384*64] ++ indices[16384*2] ++ values[16384*2]
// ---------------------------------------------------------------------------

#define D_DIM   4096
#define E_DIM   64
#define NROWS   16384
#define ROWS_PER_BLK 128
#define THREADS 256
#define KC      64
#define NCHUNK  (D_DIM / KC)

// smem layout (bytes)
#define A_TILE    (ROWS_PER_BLK * 128)       // 16384 B : 128 rows x 64 k fp16
#define SM_AHI(b) ((b) * 2 * A_TILE)
#define SM_ALO(b) ((b) * 2 * A_TILE + A_TILE)
#define SM_W      (4 * A_TILE)               // 65536
#define W_TILE    (E_DIM * 128)              // 8192 B : 64 e x 64 k fp16
#define SM_WHI(s) (SM_W + (s) * 2 * W_TILE)
#define SM_WLO(s) (SM_W + (s) * 2 * W_TILE + W_TILE)
#define SMEM_BYTES (SM_W + 6 * W_TILE)       // 114688

#define LG_STRIDE 68                          // logits smem reuses A region

#define SWZ(o) ((o) ^ (((o) >> 3) & 0x70))

// pre-split W (scaled by 64) in fp16, [e][k] row-major
__device__ __half g_Whi[E_DIM * D_DIM];
__device__ __half g_Wlo[E_DIM * D_DIM];

// ---------------- PTX helpers -----------------------------------------------
__device__ __forceinline__ void cp16(uint32_t dst, const void* src) {
    asm volatile("cp.async.cg.shared.global [%0], [%1], 16;" :: "r"(dst), "l"(src));
}
__device__ __forceinline__ void cp_commit() {
    asm volatile("cp.async.commit_group;");
}
__device__ __forceinline__ void cp_wait1() {
    asm volatile("cp.async.wait_group 1;" ::: "memory");
}
__device__ __forceinline__ void cp_wait0() {
    asm volatile("cp.async.wait_group 0;" ::: "memory");
}
__device__ __forceinline__ void ldsm4(uint32_t addr, uint32_t& r0, uint32_t& r1,
                                      uint32_t& r2, uint32_t& r3) {
    asm volatile("ldmatrix.sync.aligned.m8n8.x4.shared.b16 {%0,%1,%2,%3}, [%4];"
                 : "=r"(r0), "=r"(r1), "=r"(r2), "=r"(r3) : "r"(addr));
}
__device__ __forceinline__ void mma16816(float& c0, float& c1, float& c2, float& c3,
                                         uint32_t a0, uint32_t a1, uint32_t a2, uint32_t a3,
                                         uint32_t b0, uint32_t b1) {
    asm volatile(
        "mma.sync.aligned.m16n8k16.row.col.f32.f16.f16.f32 "
        "{%0,%1,%2,%3}, {%4,%5,%6,%7}, {%8,%9}, {%0,%1,%2,%3};"
        : "+f"(c0), "+f"(c1), "+f"(c2), "+f"(c3)
        : "r"(a0), "r"(a1), "r"(a2), "r"(a3), "r"(b0), "r"(b1));
}

// ---------------- W prep kernel ----------------------------------------------
__global__ void prep_W(const float* __restrict__ W) {
    int i = blockIdx.x * blockDim.x + threadIdx.x;   // 0 .. 262143
    float v = W[i] * 64.0f;
    __half h = __float2half_rn(v);
    g_Whi[i] = h;
    g_Wlo[i] = __float2half_rn(v - __half2float(h));
}

// ---------------- main kernel -------------------------------------------------
__global__ void __launch_bounds__(THREADS, 1)
router_kernel(const float* __restrict__ x, float* __restrict__ out)
{
    extern __shared__ char smem[];
    const int t    = threadIdx.x;
    const int w    = t >> 5;          // warp 0..7, owns rows [16w, 16w+16)
    const int lane = t & 31;
    const int row0 = blockIdx.x * ROWS_PER_BLK;
    const uint32_t sbase = (uint32_t)__cvta_generic_to_shared(smem);

    // ldmatrix lane decomposition
    const int lg = lane >> 3;         // group 0..3
    const int li = lane & 7;          // row-within-matrix

    // x loader mapping: 4 items/thread, item = (row, k-octet)
    int irow[4], ig[4];
#pragma unroll
    for (int it = 0; it < 4; ++it) {
        int id = it * THREADS + t;
        irow[it] = id >> 3;
        ig[it]   = id & 7;
    }

    // ---- prologue: W chunk 0 via cp.async; x chunk 0 via LDG ----
#pragma unroll
    for (int it = 0; it < 4; ++it) {
        int id = it * THREADS + t;
        int split = id >> 9;
        int wi = id & 511;
        int e = wi >> 3, q = wi & 7;
        uint32_t dst = sbase + (split ? SM_WLO(0) : SM_WHI(0)) + SWZ(e * 128 + q * 16);
        const __half* src = (split ? g_Wlo : g_Whi) + (size_t)e * D_DIM + q * 8;
        cp16(dst, src);
    }
    cp_commit();

    float R[4][8];
#pragma unroll
    for (int it = 0; it < 4; ++it) {
        const float4* p = (const float4*)(x + (size_t)(row0 + irow[it]) * D_DIM + ig[it] * 8);
        float4 a = p[0], b2 = p[1];
        R[it][0]=a.x;  R[it][1]=a.y;  R[it][2]=a.z;  R[it][3]=a.w;
        R[it][4]=b2.x; R[it][5]=b2.y; R[it][6]=b2.z; R[it][7]=b2.w;
    }

    // accumulators: 8 n-tiles x 4 f32 (rows l/4, l/4+8; cols 2(l%4), +1)
    float acc[8][4];
#pragma unroll
    for (int j = 0; j < 8; ++j)
#pragma unroll
        for (int q = 0; q < 4; ++q) acc[j][q] = 0.f;

    // precomputed ldmatrix byte offsets (within a tile)
    // A: g0:(R+i,k0) g1:(R+8+i,k0) g2:(R+i,k0+8) g3:(R+8+i,k0+8)
    const int arow = 16 * w + li + ((lg & 1) ? 8 : 0);
    const uint32_t aoff_base = (uint32_t)(arow * 128 + ((lg & 2) ? 16 : 0));
    // B: g0:(e0+i,k0) g1:(e0+i,k0+8) g2:(e0+8+i,k0) g3:(e0+8+i,k0+8)
    const int berow = li + ((lg & 2) ? 8 : 0);
    const uint32_t boff_base = (uint32_t)(berow * 128 + ((lg & 1) ? 16 : 0));

    for (int c = 0; c < NCHUNK; ++c) {
        const int b = c & 1;

        // ---- convert chunk c (regs R) -> fp16 hi/lo A tiles, buf b ----
#pragma unroll
        for (int it = 0; it < 4; ++it) {
            uint32_t hv[4], lv[4];
#pragma unroll
            for (int j = 0; j < 4; ++j) {
                float v0 = R[it][2*j]     * 16.0f;
                float v1 = R[it][2*j + 1] * 16.0f;
                __half2 hh = __floats2half2_rn(v0, v1);
                float2 hf  = __half22float2(hh);
                __half2 ll = __floats2half2_rn(v0 - hf.x, v1 - hf.y);
                hv[j] = *reinterpret_cast<uint32_t*>(&hh);
                lv[j] = *reinterpret_cast<uint32_t*>(&ll);
            }
            uint32_t off = SWZ(irow[it] * 128 + ig[it] * 16);
            *(uint4*)(smem + SM_AHI(b) + off) = make_uint4(hv[0], hv[1], hv[2], hv[3]);
            *(uint4*)(smem + SM_ALO(b) + off) = make_uint4(lv[0], lv[1], lv[2], lv[3]);
        }

        // ---- prefetch chunk c+1 ----
        if (c + 1 < NCHUNK) {
#pragma unroll
            for (int it = 0; it < 4; ++it) {
                const float4* p = (const float4*)
                    (x + (size_t)(row0 + irow[it]) * D_DIM + (c + 1) * KC + ig[it] * 8);
                float4 a = p[0], b2 = p[1];
                R[it][0]=a.x;  R[it][1]=a.y;  R[it][2]=a.z;  R[it][3]=a.w;
                R[it][4]=b2.x; R[it][5]=b2.y; R[it][6]=b2.z; R[it][7]=b2.w;
            }
            const int slot = (c + 1) % 3;
#pragma unroll
            for (int it = 0; it < 4; ++it) {
                int id = it * THREADS + t;
                int split = id >> 9;
                int wi = id & 511;
                int e = wi >> 3, q = wi & 7;
                uint32_t dst = sbase + (split ? SM_WLO(slot) : SM_WHI(slot))
                             + SWZ(e * 128 + q * 16);
                const __half* src = (split ? g_Wlo : g_Whi)
                                  + (size_t)e * D_DIM + (c + 1) * KC + q * 8;
                cp16(dst, src);
            }
            cp_commit();
            cp_wait1();     // W chunk c resident, chunk c+1 in flight
        } else {
            cp_wait0();
        }
        __syncthreads();

        // ---- compute: 4 k16-steps, fp16x3 (hi*hi + hi*lo + lo*hi) ----
        const uint32_t ahi_base = sbase + SM_AHI(b);
        const uint32_t alo_base = sbase + SM_ALO(b);
        const uint32_t whi_base = sbase + SM_WHI(c % 3);
        const uint32_t wlo_base = sbase + SM_WLO(c % 3);

#pragma unroll
        for (int s = 0; s < 4; ++s) {
            const uint32_t aoff = SWZ(aoff_base + s * 32);
            uint32_t ah0, ah1, ah2, ah3, al0, al1, al2, al3;
            ldsm4(ahi_base + aoff, ah0, ah1, ah2, ah3);
            ldsm4(alo_base + aoff, al0, al1, al2, al3);

#pragma unroll
            for (int p = 0; p < 4; ++p) {   // expert pair-tile: e0 = 16p
                const uint32_t boff = SWZ(boff_base + (uint32_t)(p * 16 * 128) + s * 32);
                uint32_t bh0, bh1, bh2, bh3, bl0, bl1, bl2, bl3;
                ldsm4(whi_base + boff, bh0, bh1, bh2, bh3);
                ldsm4(wlo_base + boff, bl0, bl1, bl2, bl3);

                float* c0 = acc[2*p];
                float* c1 = acc[2*p + 1];
                mma16816(c0[0], c0[1], c0[2], c0[3], ah0, ah1, ah2, ah3, bh0, bh1);
                mma16816(c1[0], c1[1], c1[2], c1[3], ah0, ah1, ah2, ah3, bh2, bh3);
                mma16816(c0[0], c0[1], c0[2], c0[3], ah0, ah1, ah2, ah3, bl0, bl1);
                mma16816(c1[0], c1[1], c1[2], c1[3], ah0, ah1, ah2, ah3, bl2, bl3);
                mma16816(c0[0], c0[1], c0[2], c0[3], al0, al1, al2, al3, bh0, bh1);
                mma16816(c1[0], c1[1], c1[2], c1[3], al0, al1, al2, al3, bh2, bh3);
            }
        }
    }

    // ---- epilogue: logits -> smem (reuse A region), softmax + top-2 ----
    __syncthreads();   // everyone done with MMA reads before overwriting smem

    float* lgm = (float*)smem;
    {
        const int r0l = 16 * w + (lane >> 2);
        const int col = 2 * (lane & 3);
        const float sc = 1.0f / 1024.0f;
#pragma unroll
        for (int j = 0; j < 8; ++j) {
            float2 v0 = make_float2(acc[j][0] * sc, acc[j][1] * sc);
            float2 v1 = make_float2(acc[j][2] * sc, acc[j][3] * sc);
            *(float2*)(lgm + r0l * LG_STRIDE + 8 * j + col) = v0;
            *(float2*)(lgm + (r0l + 8) * LG_STRIDE + 8 * j + col) = v1;
        }
    }
    __syncthreads();

    if (t < ROWS_PER_BLK) {
        float l[64];
#pragma unroll
        for (int j = 0; j < 16; ++j) {
            float4 v = *(const float4*)(lgm + t * LG_STRIDE + 4 * j);
            l[4*j+0] = v.x; l[4*j+1] = v.y; l[4*j+2] = v.z; l[4*j+3] = v.w;
        }

        float mx = l[0];
#pragma unroll
        for (int j = 1; j < 64; ++j) mx = fmaxf(mx, l[j]);

        float v1 = -3.4e38f, v2 = -3.4e38f;
        int   i1 = 0,        i2 = 0;
#pragma unroll
        for (int j = 0; j < 64; ++j) {
            float lj = l[j];
            if (lj > v1)      { v2 = v1; i2 = i1; v1 = lj; i1 = j; }
            else if (lj > v2) { v2 = lj; i2 = j; }
        }

        float p[64], s = 0.f;
#pragma unroll
        for (int j = 0; j < 64; ++j) { p[j] = __expf(l[j] - mx); s += p[j]; }
        float inv = __fdividef(1.0f, s);

        const int grow = row0 + t;
        float* po = out + (size_t)grow * 64;
#pragma unroll
        for (int j = 0; j < 16; ++j) {
            float4 v;
            v.x = p[4*j+0] * inv; v.y = p[4*j+1] * inv;
            v.z = p[4*j+2] * inv; v.w = p[4*j+3] * inv;
            *(float4*)(po + 4 * j) = v;
        }
        float* io = out + (size_t)NROWS * 64;
        io[(size_t)grow * 2 + 0] = (float)i1;
        io[(size_t)grow * 2 + 1] = (float)i2;
        float* vo = out + (size_t)NROWS * 64 + (size_t)NROWS * 2;
        vo[(size_t)grow * 2 + 0] = __expf(v1 - mx) * inv;
        vo[(size_t)grow * 2 + 1] = __expf(v2 - mx) * inv;
    }
}

// ---------------------------------------------------------------------------
extern "C" void kernel_launch(void* const* d_in, const int* in_sizes, int n_in,
                              void* d_out, int out_size) {
    const float* x = (const float*)d_in[0];
    const float* W = (const float*)d_in[1];
    float* out = (float*)d_out;

    prep_W<<<(E_DIM * D_DIM) / 256, 256>>>(W);

    cudaFuncSetAttribute(router_kernel,
                         cudaFuncAttributeMaxDynamicSharedMemorySize, SMEM_BYTES);
    router_kernel<<<NROWS / ROWS_PER_BLK, THREADS, SMEM_BYTES>>>(x, out);
}

// round 5
// speedup vs baseline: 3.6493x; 1.0706x over previous
#include <cuda_runtime.h>
#include <cuda_fp16.h>
#include <stdint.h>

// ---------------------------------------------------------------------------
// TopK Router via warp-specialized HMMA fp16x3 split GEMM.
// logits = x @ W^T : [16384, 64], softmax, top-2.
// x: [4,4096,4096] f32   W: [64,4096] f32
// out f32: probs[16384*64] ++ indices[16384*2] ++ values[16384*2]
// warps 0-3: consumers (32 rows each, LDSM+MMA). warps 4-7: producers.
// ---------------------------------------------------------------------------

#define D_DIM   4096
#define E_DIM   64
#define NROWS   16384
#define ROWS_PER_BLK 128
#define THREADS 256
#define KC      64
#define NCHUNK  (D_DIM / KC)

// smem layout (bytes)
#define A_TILE    (ROWS_PER_BLK * 128)       // 16384 B : 128 rows x 64 k fp16
#define SM_AHI(b) ((b) * 2 * A_TILE)
#define SM_ALO(b) ((b) * 2 * A_TILE + A_TILE)
#define SM_W      (4 * A_TILE)               // 65536
#define W_TILE    (E_DIM * 128)              // 8192 B : 64 e x 64 k fp16
#define SM_WHI(s) (SM_W + (s) * 2 * W_TILE)
#define SM_WLO(s) (SM_W + (s) * 2 * W_TILE + W_TILE)
#define SMEM_BYTES (SM_W + 6 * W_TILE)       // 114688

#define LG_STRIDE 68                          // logits reuse A region

#define SWZ(o) ((o) ^ (((o) >> 3) & 0x70))

// pre-split W (scaled by 64) in fp16, [e][k] row-major
__device__ __half g_Whi[E_DIM * D_DIM];
__device__ __half g_Wlo[E_DIM * D_DIM];

// ---------------- PTX helpers -----------------------------------------------
__device__ __forceinline__ void cp16(uint32_t dst, const void* src) {
    asm volatile("cp.async.cg.shared.global [%0], [%1], 16;" :: "r"(dst), "l"(src));
}
__device__ __forceinline__ void cp_commit() {
    asm volatile("cp.async.commit_group;");
}
__device__ __forceinline__ void cp_wait1() {
    asm volatile("cp.async.wait_group 1;" ::: "memory");
}
__device__ __forceinline__ void cp_wait0() {
    asm volatile("cp.async.wait_group 0;" ::: "memory");
}
__device__ __forceinline__ void ldsm4(uint32_t addr, uint32_t* r) {
    asm volatile("ldmatrix.sync.aligned.m8n8.x4.shared.b16 {%0,%1,%2,%3}, [%4];"
                 : "=r"(r[0]), "=r"(r[1]), "=r"(r[2]), "=r"(r[3]) : "r"(addr));
}
__device__ __forceinline__ void mma16816(float* c,
                                         const uint32_t* a,
                                         uint32_t b0, uint32_t b1) {
    asm volatile(
        "mma.sync.aligned.m16n8k16.row.col.f32.f16.f16.f32 "
        "{%0,%1,%2,%3}, {%4,%5,%6,%7}, {%8,%9}, {%0,%1,%2,%3};"
        : "+f"(c[0]), "+f"(c[1]), "+f"(c[2]), "+f"(c[3])
        : "r"(a[0]), "r"(a[1]), "r"(a[2]), "r"(a[3]), "r"(b0), "r"(b1));
}

// ---------------- W prep kernel ----------------------------------------------
__global__ void prep_W(const float* __restrict__ W) {
    int i = blockIdx.x * blockDim.x + threadIdx.x;   // 0 .. 262143
    float v = W[i] * 64.0f;
    __half h = __float2half_rn(v);
    g_Whi[i] = h;
    g_Wlo[i] = __float2half_rn(v - __half2float(h));
}

// ---------------- producer helpers -------------------------------------------
// x loader: 8 items/producer-thread, item = (row, k-octet of 8 floats)
__device__ __forceinline__ void ldg_chunk(float R[8][8], const float* __restrict__ x,
                                          int row0, int c0, int pt) {
#pragma unroll
    for (int it = 0; it < 8; ++it) {
        int id = it * 128 + pt;
        int row = id >> 3, g = id & 7;
        const float4* p = (const float4*)(x + (size_t)(row0 + row) * D_DIM + c0 + g * 8);
        float4 a = p[0], b = p[1];
        R[it][0]=a.x; R[it][1]=a.y; R[it][2]=a.z; R[it][3]=a.w;
        R[it][4]=b.x; R[it][5]=b.y; R[it][6]=b.z; R[it][7]=b.w;
    }
}
__device__ __forceinline__ void convert_chunk(const float R[8][8], char* smem,
                                              int buf, int pt) {
#pragma unroll
    for (int it = 0; it < 8; ++it) {
        int id = it * 128 + pt;
        int row = id >> 3, g = id & 7;
        uint32_t hv[4], lv[4];
#pragma unroll
        for (int j = 0; j < 4; ++j) {
            float v0 = R[it][2*j]     * 16.0f;
            float v1 = R[it][2*j + 1] * 16.0f;
            __half2 hh = __floats2half2_rn(v0, v1);
            float2 hf  = __half22float2(hh);
            __half2 ll = __floats2half2_rn(v0 - hf.x, v1 - hf.y);
            hv[j] = *reinterpret_cast<uint32_t*>(&hh);
            lv[j] = *reinterpret_cast<uint32_t*>(&ll);
        }
        uint32_t off = SWZ(row * 128 + g * 16);
        *(uint4*)(smem + SM_AHI(buf) + off) = make_uint4(hv[0], hv[1], hv[2], hv[3]);
        *(uint4*)(smem + SM_ALO(buf) + off) = make_uint4(lv[0], lv[1], lv[2], lv[3]);
    }
}
__device__ __forceinline__ void cpW_chunk(uint32_t sbase, int c, int pt) {
    const int slot = c % 3;
#pragma unroll
    for (int it = 0; it < 8; ++it) {
        int id = it * 128 + pt;
        int split = id >> 9;
        int wi = id & 511;
        int e = wi >> 3, q = wi & 7;
        uint32_t dst = sbase + (split ? SM_WLO(slot) : SM_WHI(slot)) + SWZ(e * 128 + q * 16);
        const __half* src = (split ? g_Wlo : g_Whi) + (size_t)e * D_DIM + c * KC + q * 8;
        cp16(dst, src);
    }
    cp_commit();
}

// ---------------- main kernel -------------------------------------------------
__global__ void __launch_bounds__(THREADS, 1)
router_kernel(const float* __restrict__ x, float* __restrict__ out)
{
    extern __shared__ char smem[];
    const int t    = threadIdx.x;
    const int lane = t & 31;
    const int row0 = blockIdx.x * ROWS_PER_BLK;
    const uint32_t sbase = (uint32_t)__cvta_generic_to_shared(smem);
    const bool consumer = (t < 128);

    // ldmatrix lane decomposition
    const int lg = lane >> 3;
    const int li = lane & 7;

    // consumer state
    const int wc = t >> 5;                     // 0..3 for consumers
    float acc[2][8][4];
#pragma unroll
    for (int m = 0; m < 2; ++m)
#pragma unroll
        for (int j = 0; j < 8; ++j)
#pragma unroll
            for (int q = 0; q < 4; ++q) acc[m][j][q] = 0.f;

    // A frag offsets (per m-tile), B frag offsets
    uint32_t aoffb[2];
#pragma unroll
    for (int m = 0; m < 2; ++m) {
        int arow = 32 * wc + 16 * m + li + ((lg & 1) ? 8 : 0);
        aoffb[m] = (uint32_t)(arow * 128 + ((lg & 2) ? 16 : 0));
    }
    const int berow = li + ((lg & 2) ? 8 : 0);
    const uint32_t boffb = (uint32_t)(berow * 128 + ((lg & 1) ? 16 : 0));

    // producer state
    const int pt = t - 128;
    float R[8][8];

    // ---- prologue (producers) ----
    if (!consumer) {
        ldg_chunk(R, x, row0, 0, pt);
        cpW_chunk(sbase, 0, pt);          // group: W0
        convert_chunk(R, smem, 0, pt);    // A0
        ldg_chunk(R, x, row0, KC, pt);    // chunk 1 -> regs
        cpW_chunk(sbase, 1, pt);          // group: W1
        cp_wait1();                       // W0 resident
    }
    __syncthreads();

    // ---- main loop ----
    for (int c = 0; c < NCHUNK; ++c) {
        if (consumer) {
            const uint32_t ahi = sbase + SM_AHI(c & 1);
            const uint32_t alo = sbase + SM_ALO(c & 1);
            const uint32_t whi = sbase + SM_WHI(c % 3);
            const uint32_t wlo = sbase + SM_WLO(c % 3);

            uint32_t fw[2][4][2][4];   // [buf][p][hi/lo][4]
            // preload W frags for s=0
#pragma unroll
            for (int p = 0; p < 4; ++p) {
                uint32_t bo = SWZ(boffb + (uint32_t)(p * 16 * 128));
                ldsm4(whi + bo, fw[0][p][0]);
                ldsm4(wlo + bo, fw[0][p][1]);
            }
#pragma unroll
            for (int s = 0; s < 4; ++s) {
                // A frags for this s
                uint32_t fa[2][2][4];  // [mt][hi/lo][4]
#pragma unroll
                for (int m = 0; m < 2; ++m) {
                    uint32_t ao = SWZ(aoffb[m] + s * 32);
                    ldsm4(ahi + ao, fa[m][0]);
                    ldsm4(alo + ao, fa[m][1]);
                }
                // prefetch W frags for s+1
                if (s < 3) {
#pragma unroll
                    for (int p = 0; p < 4; ++p) {
                        uint32_t bo = SWZ(boffb + (uint32_t)(p * 16 * 128) + (s + 1) * 32);
                        ldsm4(whi + bo, fw[(s + 1) & 1][p][0]);
                        ldsm4(wlo + bo, fw[(s + 1) & 1][p][1]);
                    }
                }
                // MMAs for s
#pragma unroll
                for (int p = 0; p < 4; ++p) {
                    const uint32_t* bh = fw[s & 1][p][0];
                    const uint32_t* bl = fw[s & 1][p][1];
#pragma unroll
                    for (int m = 0; m < 2; ++m) {
                        float* c0 = acc[m][2 * p];
                        float* c1 = acc[m][2 * p + 1];
                        mma16816(c0, fa[m][0], bh[0], bh[1]);
                        mma16816(c1, fa[m][0], bh[2], bh[3]);
                        mma16816(c0, fa[m][0], bl[0], bl[1]);
                        mma16816(c1, fa[m][0], bl[2], bl[3]);
                        mma16816(c0, fa[m][1], bh[0], bh[1]);
                        mma16816(c1, fa[m][1], bh[2], bh[3]);
                    }
                }
            }
        } else {
            if (c + 1 < NCHUNK) convert_chunk(R, smem, (c + 1) & 1, pt);
            if (c + 2 < NCHUNK) {
                ldg_chunk(R, x, row0, (c + 2) * KC, pt);
                cpW_chunk(sbase, c + 2, pt);
                cp_wait1();    // W(c+1) resident
            } else if (c + 1 < NCHUNK) {
                cp_wait0();    // last W resident
            }
        }
        __syncthreads();
    }

    // ---- epilogue: logits -> smem (reuse A region) ----
    float* lgm = (float*)smem;
    if (consumer) {
        const int r_in = lane >> 2;
        const int col  = 2 * (lane & 3);
        const float sc = 1.0f / 1024.0f;
#pragma unroll
        for (int m = 0; m < 2; ++m) {
            const int rb = 32 * wc + 16 * m + r_in;
#pragma unroll
            for (int j = 0; j < 8; ++j) {
                *(float2*)(lgm + rb * LG_STRIDE + 8 * j + col)
                    = make_float2(acc[m][j][0] * sc, acc[m][j][1] * sc);
                *(float2*)(lgm + (rb + 8) * LG_STRIDE + 8 * j + col)
                    = make_float2(acc[m][j][2] * sc, acc[m][j][3] * sc);
            }
        }
    }
    __syncthreads();

    if (t < ROWS_PER_BLK) {
        float l[64];
#pragma unroll
        for (int j = 0; j < 16; ++j) {
            float4 v = *(const float4*)(lgm + t * LG_STRIDE + 4 * j);
            l[4*j+0] = v.x; l[4*j+1] = v.y; l[4*j+2] = v.z; l[4*j+3] = v.w;
        }

        float mx = l[0];
#pragma unroll
        for (int j = 1; j < 64; ++j) mx = fmaxf(mx, l[j]);

        float v1 = -3.4e38f, v2 = -3.4e38f;
        int   i1 = 0,        i2 = 0;
#pragma unroll
        for (int j = 0; j < 64; ++j) {
            float lj = l[j];
            if (lj > v1)      { v2 = v1; i2 = i1; v1 = lj; i1 = j; }
            else if (lj > v2) { v2 = lj; i2 = j; }
        }

        float p[64], s = 0.f;
#pragma unroll
        for (int j = 0; j < 64; ++j) { p[j] = __expf(l[j] - mx); s += p[j]; }
        float inv = __fdividef(1.0f, s);

        const int grow = row0 + t;
        float* po = out + (size_t)grow * 64;
#pragma unroll
        for (int j = 0; j < 16; ++j) {
            float4 v;
            v.x = p[4*j+0] * inv; v.y = p[4*j+1] * inv;
            v.z = p[4*j+2] * inv; v.w = p[4*j+3] * inv;
            *(float4*)(po + 4 * j) = v;
        }
        float* io = out + (size_t)NROWS * 64;
        io[(size_t)grow * 2 + 0] = (float)i1;
        io[(size_t)grow * 2 + 1] = (float)i2;
        float* vo = out + (size_t)NROWS * 64 + (size_t)NROWS * 2;
        vo[(size_t)grow * 2 + 0] = __expf(v1 - mx) * inv;
        vo[(size_t)grow * 2 + 1] = __expf(v2 - mx) * inv;
    }
}

// ---------------------------------------------------------------------------
extern "C" void kernel_launch(void* const* d_in, const int* in_sizes, int n_in,
                              void* d_out, int out_size) {
    const float* x = (const float*)d_in[0];
    const float* W = (const float*)d_in[1];
    float* out = (float*)d_out;

    prep_W<<<(E_DIM * D_DIM) / 256, 256>>>(W);

    cudaFuncSetAttribute(router_kernel,
                         cudaFuncAttributeMaxDynamicSharedMemorySize, SMEM_BYTES);
    router_kernel<<<NROWS / ROWS_PER_BLK, THREADS, SMEM_BYTES>>>(x, out);
}